// round 5
// baseline (speedup 1.0000x reference)
#include <cuda_runtime.h>
#include <cstdint>

// ---------------------------------------------------------------------------
// MotionGenerator seq2seq LSTM (B=512, H=512, L=2, T=120) — single persistent
// kernel, grid barriers, gate-permuted GEMM with fused LSTM pointwise.
// ---------------------------------------------------------------------------

#define BSZ   512
#define HDIM  512
#define TLEN  120
#define FDIM  72
#define G4H   2048
#define INW   713
#define SH    (BSZ * HDIM)

#define NCTA  128
#define NTHR  128
#define GSTRIDE (NCTA * NTHR)

// ------------------------- scratch (device globals) ------------------------
__device__ float g_encin[BSZ * TLEN * HDIM];   // [b*TLEN+t][h]
__device__ float g_h[4][SH];                   // [layer*2 + parity][b*H+j]
__device__ float g_c[2][SH];                   // [layer][b*H+j]
__device__ float g_x[SH];                      // decoder embedded input
__device__ float g_cpart[SH];                  // cond @ Wcond^T + emb_b
__device__ float g_bperm[4][G4H];              // gate-permuted bih+bhh per layer
__device__ unsigned g_bar_cnt = 0;
__device__ unsigned g_bar_gen = 0;

// ------------------------------- grid barrier ------------------------------
__device__ __forceinline__ void gridbar() {
    __syncthreads();
    if (threadIdx.x == 0) {
        unsigned gen = *((volatile unsigned*)&g_bar_gen);
        __threadfence();
        if (atomicAdd(&g_bar_cnt, 1u) == NCTA - 1) {
            g_bar_cnt = 0;
            __threadfence();
            atomicExch(&g_bar_gen, gen + 1);
        } else {
            while (*((volatile unsigned*)&g_bar_gen) == gen) { }
        }
    }
    __syncthreads();
    __threadfence();
}

// ------------------------------ helpers ------------------------------------
#define FMA2(ac, pa_, pb_) \
    asm("fma.rn.f32x2 %0, %1, %2, %0;" : "+l"(ac) : "l"(pa_), "l"(pb_))

__device__ __forceinline__ float lo2(unsigned long long v) {
    return __uint_as_float((unsigned)(v & 0xffffffffull));
}
__device__ __forceinline__ float hi2(unsigned long long v) {
    return __uint_as_float((unsigned)(v >> 32));
}
__device__ __forceinline__ float sigm(float x) { return 1.f / (1.f + expf(-x)); }

// ---------------------------------------------------------------------------
// One LSTM cell: gates = X@Wih^T + Hin@Whh^T + bias (gate-permuted columns),
// fused pointwise epilogue writes Hout, updates C in place.
// Tile 64(M) x 128(N'), 128 threads, 8x8 micro-tile, f32x2 packed FMA.
// Column permutation: N' = 4*j + g  (g in {i,f,g,o}), orig row = g*512 + j.
// Grid must be exactly 128 CTAs = 8 Mtiles x 16 Ntiles.
// ---------------------------------------------------------------------------
__device__ __noinline__ void cell_phase(
    const float* __restrict__ X, int ldx,
    const float* __restrict__ Hin,
    const float* __restrict__ Wih,
    const float* __restrict__ Whh,
    const float* __restrict__ bperm,
    float* __restrict__ Hout,
    float* __restrict__ C,
    float (*As)[68], float (*Bs)[132])
{
    int tid = threadIdx.x;
    int blk = blockIdx.x;
    int bm = (blk & 7) * 64;
    int bn = (blk >> 3) * 128;
    int tx = tid & 15, ty = tid >> 4;
    int tx8 = tx * 8, ty8 = ty * 8;
    int arow = tid >> 1, ak = (tid & 1) * 8;
    int brow = tid;
    int borig = ((bn + brow) & 3) * 512 + ((bn + brow) >> 2);

    unsigned long long acc[8][4];
#pragma unroll
    for (int i = 0; i < 8; i++)
#pragma unroll
        for (int q = 0; q < 4; q++) acc[i][q] = 0ull;

    const float* Arow0 = X + (size_t)(bm + arow) * ldx;
    const float* Arow1 = Hin + (size_t)(bm + arow) * HDIM;
    const float* Brow0 = Wih + (size_t)borig * HDIM;
    const float* Brow1 = Whh + (size_t)borig * HDIM;

    float4 pa0 = *(const float4*)(Arow0 + ak);
    float4 pa1 = *(const float4*)(Arow0 + ak + 4);
    float4 pb0 = *(const float4*)(Brow0 + 0);
    float4 pb1 = *(const float4*)(Brow0 + 4);
    float4 pb2 = *(const float4*)(Brow0 + 8);
    float4 pb3 = *(const float4*)(Brow0 + 12);

#pragma unroll 1
    for (int it = 0; it < 64; it++) {
        As[ak + 0][arow] = pa0.x; As[ak + 1][arow] = pa0.y;
        As[ak + 2][arow] = pa0.z; As[ak + 3][arow] = pa0.w;
        As[ak + 4][arow] = pa1.x; As[ak + 5][arow] = pa1.y;
        As[ak + 6][arow] = pa1.z; As[ak + 7][arow] = pa1.w;
        Bs[0][brow] = pb0.x;  Bs[1][brow] = pb0.y;
        Bs[2][brow] = pb0.z;  Bs[3][brow] = pb0.w;
        Bs[4][brow] = pb1.x;  Bs[5][brow] = pb1.y;
        Bs[6][brow] = pb1.z;  Bs[7][brow] = pb1.w;
        Bs[8][brow] = pb2.x;  Bs[9][brow] = pb2.y;
        Bs[10][brow] = pb2.z; Bs[11][brow] = pb2.w;
        Bs[12][brow] = pb3.x; Bs[13][brow] = pb3.y;
        Bs[14][brow] = pb3.z; Bs[15][brow] = pb3.w;
        __syncthreads();

        if (it < 63) {
            int nit = it + 1;
            const float* Ar = (nit < 32) ? Arow0 : Arow1;
            const float* Br = (nit < 32) ? Brow0 : Brow1;
            int kk = (nit & 31) * 16;
            pa0 = *(const float4*)(Ar + kk + ak);
            pa1 = *(const float4*)(Ar + kk + ak + 4);
            pb0 = *(const float4*)(Br + kk + 0);
            pb1 = *(const float4*)(Br + kk + 4);
            pb2 = *(const float4*)(Br + kk + 8);
            pb3 = *(const float4*)(Br + kk + 12);
        }

#pragma unroll
        for (int k = 0; k < 16; k++) {
            float4 a0 = *(const float4*)&As[k][ty8];
            float4 a1 = *(const float4*)&As[k][ty8 + 4];
            ulonglong2 bq0 = *(const ulonglong2*)&Bs[k][tx8];
            ulonglong2 bq1 = *(const ulonglong2*)&Bs[k][tx8 + 4];
            float av[8] = {a0.x, a0.y, a0.z, a0.w, a1.x, a1.y, a1.z, a1.w};
            unsigned long long bv0 = bq0.x, bv1 = bq0.y, bv2 = bq1.x, bv3 = bq1.y;
#pragma unroll
            for (int i = 0; i < 8; i++) {
                unsigned long long p;
                unsigned u = __float_as_uint(av[i]);
                asm("mov.b64 %0,{%1,%1};" : "=l"(p) : "r"(u));
                FMA2(acc[i][0], p, bv0);
                FMA2(acc[i][1], p, bv1);
                FMA2(acc[i][2], p, bv2);
                FMA2(acc[i][3], p, bv3);
            }
        }
        __syncthreads();
    }

    // fused LSTM pointwise epilogue
    const float* bp = bperm + bn + tx8;
    int j0 = (bn + tx8) >> 2;
#pragma unroll
    for (int i = 0; i < 8; i++) {
        int b = bm + ty8 + i;
#pragma unroll
        for (int jj = 0; jj < 2; jj++) {
            float gi = lo2(acc[i][2 * jj + 0]) + bp[4 * jj + 0];
            float gf = hi2(acc[i][2 * jj + 0]) + bp[4 * jj + 1];
            float gg = lo2(acc[i][2 * jj + 1]) + bp[4 * jj + 2];
            float go = hi2(acc[i][2 * jj + 1]) + bp[4 * jj + 3];
            int idx = b * HDIM + j0 + jj;
            float cn = sigm(gf) * C[idx] + sigm(gi) * tanhf(gg);
            C[idx] = cn;
            Hout[idx] = sigm(go) * tanhf(cn);
        }
    }
}

// ------------------------------ persistent kernel --------------------------
__global__ void __launch_bounds__(NTHR, 1) motion_persistent(
    const float* __restrict__ label,
    const float* __restrict__ ce,
    const float* __restrict__ traj,
    const float* __restrict__ enc_emb_W,
    const float* __restrict__ enc_emb_b,
    const float* __restrict__ prelu_a,
    const float* __restrict__ emb_W,
    const float* __restrict__ emb_b,
    const float* __restrict__ out_W,
    const float* __restrict__ out_b,
    const float* __restrict__ enc_Wih,
    const float* __restrict__ enc_Whh,
    const float* __restrict__ enc_bih,
    const float* __restrict__ enc_bhh,
    const float* __restrict__ dec_Wih,
    const float* __restrict__ dec_Whh,
    const float* __restrict__ dec_bih,
    const float* __restrict__ dec_bhh,
    float* __restrict__ out)
{
    __shared__ float As[16][68];
    __shared__ float Bs[16][132];

    const int gtid = blockIdx.x * NTHR + threadIdx.x;
    const size_t WOFF = (size_t)G4H * HDIM;   // per-layer weight stride
    const float pa = prelu_a[0];

    // ------------------------------- prep ---------------------------------
    for (int i = gtid; i < 4 * SH; i += GSTRIDE) ((float*)g_h)[i] = 0.f;
    for (int i = gtid; i < 2 * SH; i += GSTRIDE) ((float*)g_c)[i] = 0.f;

    for (int i = gtid; i < 4 * G4H; i += GSTRIDE) {
        int l = i >> 11, np = i & (G4H - 1);
        int orig = (np & 3) * 512 + (np >> 2);
        float v;
        if (l == 0)      v = enc_bih[orig] + enc_bhh[orig];
        else if (l == 1) v = enc_bih[G4H + orig] + enc_bhh[G4H + orig];
        else if (l == 2) v = dec_bih[orig] + dec_bhh[orig];
        else             v = dec_bih[G4H + orig] + dec_bhh[G4H + orig];
        ((float*)g_bperm)[i] = v;
    }

    for (int i = gtid; i < BSZ * TLEN * HDIM; i += GSTRIDE) {
        int bt = i >> 9, h = i & 511;
        float v = fmaf(enc_emb_W[h * 3 + 0], traj[bt * 3 + 0],
                   fmaf(enc_emb_W[h * 3 + 1], traj[bt * 3 + 1],
                    fmaf(enc_emb_W[h * 3 + 2], traj[bt * 3 + 2], enc_emb_b[h])));
        g_encin[i] = (v >= 0.f) ? v : pa * v;
    }

    for (int i = gtid; i < SH; i += GSTRIDE) {
        int b = i >> 9, h = i & 511;
        const float* w = emb_W + (size_t)h * INW + FDIM;
        const float* lb = label + b * 10;
        const float* cb = ce + b * 64;
        float acc = emb_b[h];
#pragma unroll 1
        for (int ii = 0; ii < 10; ii++) {
            float lv = lb[ii];
            const float* wr = w + ii * 64;
#pragma unroll 8
            for (int jj = 0; jj < 64; jj++)
                acc = fmaf(lv * cb[jj], wr[jj], acc);
        }
        g_cpart[i] = acc;
    }
    gridbar();

    // ------------------------------ encoder -------------------------------
    for (int t = 0; t < TLEN; t++) {
        int p = t & 1;
        cell_phase(g_encin + (size_t)t * HDIM, TLEN * HDIM,
                   g_h[0 + p], enc_Wih, enc_Whh, g_bperm[0],
                   g_h[0 + (p ^ 1)], g_c[0], As, Bs);
        gridbar();
        cell_phase(g_h[0 + (p ^ 1)], HDIM,
                   g_h[2 + p], enc_Wih + WOFF, enc_Whh + WOFF, g_bperm[1],
                   g_h[2 + (p ^ 1)], g_c[1], As, Bs);
        gridbar();
    }

    // ------------------------------ decoder -------------------------------
    for (int t = 0; t < TLEN; t++) {
        int p = t & 1;
        // embedding phase: x = prelu(cpart + ts*w712 + dec_in @ W[:, :72])
        float ts = (float)(t + 1) * (1.0f / (float)TLEN);
        for (int i = gtid; i < SH; i += GSTRIDE) {
            int b = i >> 9, h = i & 511;
            const float* w = emb_W + (size_t)h * INW;
            float acc = g_cpart[i] + ts * w[712];
            if (t > 0) {
                const float* dn = out + ((size_t)b * TLEN + (t - 1)) * FDIM;
#pragma unroll
                for (int f = 0; f < FDIM; f++) acc = fmaf(dn[f], w[f], acc);
            }
            g_x[i] = (acc >= 0.f) ? acc : pa * acc;
        }
        gridbar();

        cell_phase(g_x, HDIM,
                   g_h[0 + p], dec_Wih, dec_Whh, g_bperm[2],
                   g_h[0 + (p ^ 1)], g_c[0], As, Bs);
        gridbar();
        cell_phase(g_h[0 + (p ^ 1)], HDIM,
                   g_h[2 + p], dec_Wih + WOFF, dec_Whh + WOFF, g_bperm[3],
                   g_h[2 + (p ^ 1)], g_c[1], As, Bs);
        gridbar();

        // output projection phase: out[b,t,f] = h1[b] @ out_W[f] + out_b[f]
        const float* h1 = g_h[2 + (p ^ 1)];
        for (int i = gtid; i < BSZ * FDIM; i += GSTRIDE) {
            int b = i / FDIM, f = i - b * FDIM;
            const float4* hv = (const float4*)(h1 + (size_t)b * HDIM);
            const float4* wv = (const float4*)(out_W + (size_t)f * HDIM);
            float acc = 0.f;
#pragma unroll 8
            for (int k = 0; k < HDIM / 4; k++) {
                float4 a = hv[k], w = wv[k];
                acc = fmaf(a.x, w.x, acc);
                acc = fmaf(a.y, w.y, acc);
                acc = fmaf(a.z, w.z, acc);
                acc = fmaf(a.w, w.w, acc);
            }
            out[((size_t)b * TLEN + t) * FDIM + f] = acc + out_b[f];
        }
        gridbar();
    }
}

// ------------------------------- host driver -------------------------------
extern "C" void kernel_launch(void* const* d_in, const int* in_sizes, int n_in,
                              void* d_out, int out_size) {
    const float* label      = (const float*)d_in[1];
    const float* ce         = (const float*)d_in[2];
    const float* traj       = (const float*)d_in[3];
    const float* enc_emb_W  = (const float*)d_in[4];
    const float* enc_emb_b  = (const float*)d_in[5];
    const float* prelu_a    = (const float*)d_in[6];
    const float* emb_W      = (const float*)d_in[7];
    const float* emb_b      = (const float*)d_in[8];
    const float* out_W      = (const float*)d_in[9];
    const float* out_b      = (const float*)d_in[10];
    const float* enc_Wih    = (const float*)d_in[11];
    const float* enc_Whh    = (const float*)d_in[12];
    const float* enc_bih    = (const float*)d_in[13];
    const float* enc_bhh    = (const float*)d_in[14];
    const float* dec_Wih    = (const float*)d_in[15];
    const float* dec_Whh    = (const float*)d_in[16];
    const float* dec_bih    = (const float*)d_in[17];
    const float* dec_bhh    = (const float*)d_in[18];

    motion_persistent<<<NCTA, NTHR>>>(
        label, ce, traj, enc_emb_W, enc_emb_b, prelu_a, emb_W, emb_b,
        out_W, out_b, enc_Wih, enc_Whh, enc_bih, enc_bhh,
        dec_Wih, dec_Whh, dec_bih, dec_bhh, (float*)d_out);
}